// round 1
// baseline (speedup 1.0000x reference)
#include <cuda_runtime.h>

#define B_ 16
#define N_ 512
#define D_ 64
#define K_ 8
#define ROWS_ (B_ * N_)          // 8192
#define SKD_ (K_ * D_)           // 512

// ---------------- static device scratch (no allocations allowed) ----------
__device__ __align__(16) int   g_adjT[B_ * N_ * N_];           // 16.8 MB
__device__ __align__(16) float g_S[2][ROWS_ * SKD_];           // 2 x 16.8 MB
__device__ __align__(16) float g_W[2][SKD_ * D_];              // 2 x 128 KB

// ---------------- kernel 1: adjacency transpose ---------------------------
// adjT[b][i][j] = adj[b][j][i]
__global__ void transpose_adj(const int* __restrict__ adj) {
    __shared__ int tile[32][33];
    int b  = blockIdx.z;
    int j0 = blockIdx.x * 32;
    int i0 = blockIdx.y * 32;
    const int* src = adj   + (size_t)b * N_ * N_;
    int*       dst = g_adjT + (size_t)b * N_ * N_;
    int tx = threadIdx.x, ty = threadIdx.y;   // 32 x 8
#pragma unroll
    for (int r = 0; r < 32; r += 8)
        tile[ty + r][tx] = src[(size_t)(i0 + ty + r) * N_ + j0 + tx];
    __syncthreads();
#pragma unroll
    for (int r = 0; r < 32; r += 8)
        dst[(size_t)(j0 + ty + r) * N_ + i0 + tx] = tile[tx][ty + r];
}

// ---------------- kernel 2: repack matrices into GEMM-friendly W ----------
// W[dir][k*64+e][d] = mat_dir[k][d][e]
__global__ void wprep(const float* __restrict__ min_, const float* __restrict__ mout_) {
    int idx = blockIdx.x * 256 + threadIdx.x;   // 0 .. 2*8*64*64-1
    int dir = idx >> 15;
    int r   = idx & 32767;
    int ke  = r >> 6;         // k*64+e
    int d   = r & 63;
    int k   = ke >> 6;
    int e   = ke & 63;
    const float* m = dir ? mout_ : min_;
    g_W[dir][ke * D_ + d] = m[(k * D_ + d) * D_ + e];
}

// ---------------- kernel 3: bucket aggregation ----------------------------
// one warp per (dir, b, i).  S[b,i,k,:] = sum_j [adj_dir==k] h[b,j,:]
__global__ void aggregate(const float* __restrict__ h, const int* __restrict__ adj) {
    __shared__ float S[8][SKD_];      // 8 warps * 2KB = 16KB
    int warp = (blockIdx.x * blockDim.x + threadIdx.x) >> 5;
    int lane = threadIdx.x & 31;
    int wl   = threadIdx.x >> 5;
    int dir  = warp >> 13;            // 8192 rows per direction
    int row  = warp & 8191;
    int b    = row >> 9;

    const int*   arow = (dir ? g_adjT : adj) + (size_t)row * N_;
    const float* hb   = h + (size_t)(b << 9) * D_;
    float* Sw = S[wl];

#pragma unroll
    for (int k = 0; k < K_; k++) {
        Sw[k * D_ + 2 * lane]     = 0.f;
        Sw[k * D_ + 2 * lane + 1] = 0.f;
    }

    for (int j0 = 0; j0 < N_; j0 += 32) {
        int kreg = __ldg(&arow[j0 + lane]);
#pragma unroll
        for (int t = 0; t < 32; t++) {
            int k = __shfl_sync(0xffffffffu, kreg, t);
            if (k) {   // k==0 means no edge -> skip (uniform branch)
                const float2 hv =
                    *reinterpret_cast<const float2*>(&hb[(size_t)(j0 + t) * D_ + 2 * lane]);
                float* sp = &Sw[(k - 1) * D_ + 2 * lane];
                float2 s = *reinterpret_cast<float2*>(sp);
                s.x += hv.x;
                s.y += hv.y;
                *reinterpret_cast<float2*>(sp) = s;
            }
        }
    }

    float* So = &g_S[dir][(size_t)row * SKD_];
#pragma unroll
    for (int k = 0; k < K_; k++)
        *reinterpret_cast<float2*>(&So[k * D_ + 2 * lane]) =
            *reinterpret_cast<const float2*>(&Sw[k * D_ + 2 * lane]);
}

// ---------------- kernel 4: GEMM + bias ------------------------------------
// out[row, dir*64 + n] = sum_ke S[dir][row][ke] * W[dir][ke][n] + bias[dir*64+n]
#define BM 64
#define BN 64
#define BK 16
__global__ void gemm_out(const float* __restrict__ bias, float* __restrict__ out) {
    int dir = blockIdx.y;
    const float* Sd = g_S[dir];
    const float* Wd = g_W[dir];

    __shared__ float As[BK][BM + 4];
    __shared__ float Bs[BK][BN + 4];

    int tid = threadIdx.x;           // 256 threads
    int tx  = tid & 15;
    int ty  = tid >> 4;
    int row0 = blockIdx.x * BM;

    float acc[4][4] = {};

    for (int kk = 0; kk < SKD_; kk += BK) {
        {   // load A tile: 64 rows x 16 k, one float4 per thread
            int m  = tid >> 2;
            int k4 = (tid & 3) * 4;
            float4 v = *reinterpret_cast<const float4*>(
                &Sd[(size_t)(row0 + m) * SKD_ + kk + k4]);
            As[k4 + 0][m] = v.x;
            As[k4 + 1][m] = v.y;
            As[k4 + 2][m] = v.z;
            As[k4 + 3][m] = v.w;
        }
        {   // load B tile: 16 k x 64 n, one float4 per thread
            int k  = tid >> 4;
            int n4 = (tid & 15) * 4;
            float4 v = *reinterpret_cast<const float4*>(&Wd[(size_t)(kk + k) * D_ + n4]);
            Bs[k][n4 + 0] = v.x;
            Bs[k][n4 + 1] = v.y;
            Bs[k][n4 + 2] = v.z;
            Bs[k][n4 + 3] = v.w;
        }
        __syncthreads();
#pragma unroll
        for (int k = 0; k < BK; k++) {
            float a[4], bb[4];
#pragma unroll
            for (int u = 0; u < 4; u++) a[u]  = As[k][ty * 4 + u];
#pragma unroll
            for (int u = 0; u < 4; u++) bb[u] = Bs[k][tx * 4 + u];
#pragma unroll
            for (int um = 0; um < 4; um++)
#pragma unroll
                for (int un = 0; un < 4; un++)
                    acc[um][un] += a[um] * bb[un];
        }
        __syncthreads();
    }

    int n = tx * 4;
    float4 bv = *reinterpret_cast<const float4*>(&bias[dir * 64 + n]);
#pragma unroll
    for (int um = 0; um < 4; um++) {
        int m = row0 + ty * 4 + um;
        float4 o;
        o.x = acc[um][0] + bv.x;
        o.y = acc[um][1] + bv.y;
        o.z = acc[um][2] + bv.z;
        o.w = acc[um][3] + bv.w;
        *reinterpret_cast<float4*>(&out[(size_t)m * 128 + dir * 64 + n]) = o;
    }
}

// ---------------- launch ----------------------------------------------------
extern "C" void kernel_launch(void* const* d_in, const int* in_sizes, int n_in,
                              void* d_out, int out_size) {
    const float* h     = (const float*)d_in[0];   // [16,512,64]
    const int*   adj   = (const int*)d_in[1];     // [16,512,512]
    // d_in[2] = distance, unused (as in reference)
    const float* min_  = (const float*)d_in[3];   // [8,64,64]
    const float* mout_ = (const float*)d_in[4];   // [8,64,64]
    const float* bias  = (const float*)d_in[5];   // [128]
    float* out = (float*)d_out;                   // [16,512,128]

    transpose_adj<<<dim3(16, 16, 16), dim3(32, 8)>>>(adj);
    wprep<<<256, 256>>>(min_, mout_);
    aggregate<<<2048, 256>>>(h, adj);             // 16384 warps = 8192 rows x 2 dirs
    gemm_out<<<dim3(128, 2), 256>>>(bias, out);
}

// round 2
// speedup vs baseline: 1.0968x; 1.0968x over previous
#include <cuda_runtime.h>

#define B_ 16
#define N_ 512
#define D_ 64
#define K_ 8
#define ROWS_ (B_ * N_)          // 8192
#define SKD_ (K_ * D_)           // 512

// ---------------- static device scratch -----------------------------------
__device__ __align__(16) int   g_adjT[B_ * N_ * N_];           // 16.8 MB
__device__ __align__(16) float g_S[2][ROWS_ * SKD_];           // 2 x 16.8 MB
__device__ __align__(16) float g_W[2][SKD_ * D_];              // 2 x 128 KB

// ---------------- f32x2 packed-FMA helpers --------------------------------
__device__ __forceinline__ unsigned long long pack2(float x, float y) {
    unsigned long long r;
    asm("mov.b64 %0, {%1, %2};" : "=l"(r) : "f"(x), "f"(y));
    return r;
}
__device__ __forceinline__ void unpack2(unsigned long long v, float& x, float& y) {
    asm("mov.b64 {%0, %1}, %2;" : "=f"(x), "=f"(y) : "l"(v));
}
__device__ __forceinline__ void fma2(unsigned long long& acc,
                                     unsigned long long a, unsigned long long b) {
    asm("fma.rn.f32x2 %0, %1, %2, %0;" : "+l"(acc) : "l"(a), "l"(b));
}

// ---------------- kernel 1: adjacency transpose ---------------------------
__global__ void transpose_adj(const int* __restrict__ adj) {
    __shared__ int tile[32][33];
    int b  = blockIdx.z;
    int j0 = blockIdx.x * 32;
    int i0 = blockIdx.y * 32;
    const int* src = adj    + (size_t)b * N_ * N_;
    int*       dst = g_adjT + (size_t)b * N_ * N_;
    int tx = threadIdx.x, ty = threadIdx.y;   // 32 x 8
#pragma unroll
    for (int r = 0; r < 32; r += 8)
        tile[ty + r][tx] = src[(size_t)(i0 + ty + r) * N_ + j0 + tx];
    __syncthreads();
#pragma unroll
    for (int r = 0; r < 32; r += 8)
        dst[(size_t)(j0 + ty + r) * N_ + i0 + tx] = tile[tx][ty + r];
}

// ---------------- kernel 2: repack matrices -------------------------------
// W[dir][k*64+e][d] = mat_dir[k][d][e]
__global__ void wprep(const float* __restrict__ min_, const float* __restrict__ mout_) {
    int idx = blockIdx.x * 256 + threadIdx.x;
    int dir = idx >> 15;
    int r   = idx & 32767;
    int ke  = r >> 6;
    int d   = r & 63;
    int k   = ke >> 6;
    int e   = ke & 63;
    const float* m = dir ? mout_ : min_;
    g_W[dir][ke * D_ + d] = m[(k * D_ + d) * D_ + e];
}

// ---------------- kernel 3: bucket aggregation (counting sort) ------------
// one warp per (dir, b, i). Builds per-k index lists in smem (ballot prefix,
// no atomics), then accumulates each bucket in registers.
__global__ void aggregate(const float* __restrict__ h, const int* __restrict__ adj) {
    __shared__ int lists[8][N_];      // 8 warps * 2KB = 16KB
    int lane = threadIdx.x & 31;
    int wl   = threadIdx.x >> 5;
    int warp = blockIdx.x * 8 + wl;
    int dir  = warp >> 13;
    int row  = warp & 8191;
    int b    = row >> 9;

    const int*   arow = (dir ? g_adjT : adj) + (size_t)row * N_;
    const float* hb   = h + (size_t)b * N_ * D_;
    int* list = lists[wl];
    unsigned lt = (1u << lane) - 1u;

    // load full adj row into registers (coalesced int4)
    int4 av[4];
#pragma unroll
    for (int c = 0; c < 4; c++)
        av[c] = reinterpret_cast<const int4*>(arow)[c * 32 + lane];

    // pass 1: histogram via ballots (identical result in every lane)
    int cnt[8] = {0, 0, 0, 0, 0, 0, 0, 0};
#pragma unroll
    for (int c = 0; c < 4; c++) {
        int vals[4] = {av[c].x, av[c].y, av[c].z, av[c].w};
#pragma unroll
        for (int u = 0; u < 4; u++) {
            int kv = vals[u];
#pragma unroll
            for (int k = 1; k <= 8; k++)
                cnt[k - 1] += __popc(__ballot_sync(0xffffffffu, kv == k));
        }
    }
    int offs[9];
    offs[0] = 0;
#pragma unroll
    for (int k = 0; k < 8; k++) offs[k + 1] = offs[k] + cnt[k];

    // pass 2: scatter j-indices into their bucket segments
    int base[8];
#pragma unroll
    for (int k = 0; k < 8; k++) base[k] = offs[k];
#pragma unroll
    for (int c = 0; c < 4; c++) {
        int vals[4] = {av[c].x, av[c].y, av[c].z, av[c].w};
#pragma unroll
        for (int u = 0; u < 4; u++) {
            int kv  = vals[u];
            int jj  = c * 128 + lane * 4 + u;
            int pos = 0;
#pragma unroll
            for (int k = 1; k <= 8; k++) {
                unsigned m = __ballot_sync(0xffffffffu, kv == k);
                if (kv == k) pos = base[k - 1] + __popc(m & lt);
                base[k - 1] += __popc(m);
            }
            if (kv) list[pos] = jj;
        }
    }
    __syncwarp();

    // pass 3: per-bucket register accumulation (4-way ILP)
    float* So = &g_S[dir][(size_t)row * SKD_];
#pragma unroll
    for (int k = 0; k < 8; k++) {
        float2 a0 = make_float2(0.f, 0.f), a1 = a0, a2 = a0, a3 = a0;
        int idx = offs[k];
        int end = offs[k + 1];
        for (; idx + 4 <= end; idx += 4) {
            int j0 = list[idx], j1 = list[idx + 1], j2 = list[idx + 2], j3 = list[idx + 3];
            float2 v0 = *reinterpret_cast<const float2*>(&hb[j0 * D_ + 2 * lane]);
            float2 v1 = *reinterpret_cast<const float2*>(&hb[j1 * D_ + 2 * lane]);
            float2 v2 = *reinterpret_cast<const float2*>(&hb[j2 * D_ + 2 * lane]);
            float2 v3 = *reinterpret_cast<const float2*>(&hb[j3 * D_ + 2 * lane]);
            a0.x += v0.x; a0.y += v0.y;
            a1.x += v1.x; a1.y += v1.y;
            a2.x += v2.x; a2.y += v2.y;
            a3.x += v3.x; a3.y += v3.y;
        }
        for (; idx < end; idx++) {
            int j0 = list[idx];
            float2 v0 = *reinterpret_cast<const float2*>(&hb[j0 * D_ + 2 * lane]);
            a0.x += v0.x; a0.y += v0.y;
        }
        float2 s;
        s.x = (a0.x + a1.x) + (a2.x + a3.x);
        s.y = (a0.y + a1.y) + (a2.y + a3.y);
        *reinterpret_cast<float2*>(&So[k * D_ + 2 * lane]) = s;
    }
}

// ---------------- kernel 4: GEMM + bias (f32x2 packed FMA) ----------------
#define BM 64
#define BN 64
#define BK 16
__global__ void gemm_out(const float* __restrict__ bias, float* __restrict__ out) {
    int dir = blockIdx.y;
    const float* Sd = g_S[dir];
    const float* Wd = g_W[dir];

    __shared__ float As[BK][BM + 4];
    __shared__ float Bs[BK][BN + 4];

    int tid  = threadIdx.x;          // 256
    int tx   = tid & 15;
    int ty   = tid >> 4;
    int row0 = blockIdx.x * BM;

    unsigned long long acc2[4][2];
#pragma unroll
    for (int um = 0; um < 4; um++) { acc2[um][0] = 0ull; acc2[um][1] = 0ull; }

    for (int kk = 0; kk < SKD_; kk += BK) {
        {
            int m  = tid >> 2;
            int k4 = (tid & 3) * 4;
            float4 v = *reinterpret_cast<const float4*>(
                &Sd[(size_t)(row0 + m) * SKD_ + kk + k4]);
            As[k4 + 0][m] = v.x;
            As[k4 + 1][m] = v.y;
            As[k4 + 2][m] = v.z;
            As[k4 + 3][m] = v.w;
        }
        {
            int k  = tid >> 4;
            int n4 = (tid & 15) * 4;
            float4 v = *reinterpret_cast<const float4*>(&Wd[(size_t)(kk + k) * D_ + n4]);
            Bs[k][n4 + 0] = v.x;
            Bs[k][n4 + 1] = v.y;
            Bs[k][n4 + 2] = v.z;
            Bs[k][n4 + 3] = v.w;
        }
        __syncthreads();
#pragma unroll
        for (int k = 0; k < BK; k++) {
            unsigned long long b2a =
                *reinterpret_cast<const unsigned long long*>(&Bs[k][tx * 4]);
            unsigned long long b2b =
                *reinterpret_cast<const unsigned long long*>(&Bs[k][tx * 4 + 2]);
#pragma unroll
            for (int um = 0; um < 4; um++) {
                float a = As[k][ty * 4 + um];
                unsigned long long a2 = pack2(a, a);
                fma2(acc2[um][0], a2, b2a);
                fma2(acc2[um][1], a2, b2b);
            }
        }
        __syncthreads();
    }

    int n = tx * 4;
    float4 bv = *reinterpret_cast<const float4*>(&bias[dir * 64 + n]);
#pragma unroll
    for (int um = 0; um < 4; um++) {
        int m = row0 + ty * 4 + um;
        float x0, x1, x2, x3;
        unpack2(acc2[um][0], x0, x1);
        unpack2(acc2[um][1], x2, x3);
        float4 o;
        o.x = x0 + bv.x;
        o.y = x1 + bv.y;
        o.z = x2 + bv.z;
        o.w = x3 + bv.w;
        *reinterpret_cast<float4*>(&out[(size_t)m * 128 + dir * 64 + n]) = o;
    }
}

// ---------------- launch ----------------------------------------------------
extern "C" void kernel_launch(void* const* d_in, const int* in_sizes, int n_in,
                              void* d_out, int out_size) {
    const float* h     = (const float*)d_in[0];   // [16,512,64]
    const int*   adj   = (const int*)d_in[1];     // [16,512,512]
    const float* min_  = (const float*)d_in[3];   // [8,64,64]
    const float* mout_ = (const float*)d_in[4];   // [8,64,64]
    const float* bias  = (const float*)d_in[5];   // [128]
    float* out = (float*)d_out;                   // [16,512,128]

    transpose_adj<<<dim3(16, 16, 16), dim3(32, 8)>>>(adj);
    wprep<<<256, 256>>>(min_, mout_);
    aggregate<<<2048, 256>>>(h, adj);             // 16384 warps = 8192 rows x 2 dirs
    gemm_out<<<dim3(128, 2), 256>>>(bias, out);
}

// round 3
// speedup vs baseline: 1.3661x; 1.2455x over previous
#include <cuda_runtime.h>
#include <cuda_fp16.h>

#define B_ 16
#define N_ 512
#define D_ 64
#define K_ 8
#define ROWS_ (B_ * N_)          // 8192
#define SKD_ (K_ * D_)           // 512

// ---------------- static device scratch -----------------------------------
__device__ __align__(16) int    g_adjT[B_ * N_ * N_];          // 16.8 MB
__device__ __align__(16) float  g_S[2][ROWS_ * SKD_];          // 2 x 16.8 MB
__device__ __align__(16) float  g_W[2][SKD_ * D_];             // 2 x 128 KB
__device__ __align__(16) __half g_h16[B_ * N_ * D_];           // 1 MB

// ---------------- f32x2 packed-FMA helpers --------------------------------
__device__ __forceinline__ unsigned long long pack2(float x, float y) {
    unsigned long long r;
    asm("mov.b64 %0, {%1, %2};" : "=l"(r) : "f"(x), "f"(y));
    return r;
}
__device__ __forceinline__ void unpack2(unsigned long long v, float& x, float& y) {
    asm("mov.b64 {%0, %1}, %2;" : "=f"(x), "=f"(y) : "l"(v));
}
__device__ __forceinline__ void fma2(unsigned long long& acc,
                                     unsigned long long a, unsigned long long b) {
    asm("fma.rn.f32x2 %0, %1, %2, %0;" : "+l"(acc) : "l"(a), "l"(b));
}

// ---------------- kernel 1: adjacency transpose ---------------------------
__global__ void transpose_adj(const int* __restrict__ adj) {
    __shared__ int tile[32][33];
    int b  = blockIdx.z;
    int j0 = blockIdx.x * 32;
    int i0 = blockIdx.y * 32;
    const int* src = adj    + (size_t)b * N_ * N_;
    int*       dst = g_adjT + (size_t)b * N_ * N_;
    int tx = threadIdx.x, ty = threadIdx.y;   // 32 x 8
#pragma unroll
    for (int r = 0; r < 32; r += 8)
        tile[ty + r][tx] = src[(size_t)(i0 + ty + r) * N_ + j0 + tx];
    __syncthreads();
#pragma unroll
    for (int r = 0; r < 32; r += 8)
        dst[(size_t)(j0 + ty + r) * N_ + i0 + tx] = tile[tx][ty + r];
}

// ---------------- kernel 2: repack matrices + h -> fp16 -------------------
// W[dir][k*64+e][d] = mat_dir[k][d][e]
__global__ void wprep(const float* __restrict__ min_, const float* __restrict__ mout_) {
    int idx = blockIdx.x * 256 + threadIdx.x;
    int dir = idx >> 15;
    int r   = idx & 32767;
    int ke  = r >> 6;
    int d   = r & 63;
    int k   = ke >> 6;
    int e   = ke & 63;
    const float* m = dir ? mout_ : min_;
    g_W[dir][ke * D_ + d] = m[(k * D_ + d) * D_ + e];
}

__global__ void hprep(const float* __restrict__ h) {
    int i = blockIdx.x * 256 + threadIdx.x;       // over half2 elements
    float2 v = reinterpret_cast<const float2*>(h)[i];
    reinterpret_cast<__half2*>(g_h16)[i] = __floats2half2_rn(v.x, v.y);
}

// ---------------- kernel 3: aggregation (smem h-tile + counting sort) -----
// 16 warps/block, 1 row per warp, whole h-batch resident in smem as fp16.
extern __shared__ char smem_raw[];

__global__ __launch_bounds__(512, 2)
void aggregate(const int* __restrict__ adj) {
    __half2* h2   = reinterpret_cast<__half2*>(smem_raw);              // 512*32 half2 = 64KB
    short*   lst  = reinterpret_cast<short*>(smem_raw + N_ * D_ * 2);  // 16*512 short = 16KB

    int lane = threadIdx.x & 31;
    int wl   = threadIdx.x >> 5;
    int warp = blockIdx.x * 16 + wl;
    int dir  = warp >> 13;
    int row  = warp & 8191;
    int b    = row >> 9;

    // cooperative load: h-batch fp16 (32 KB) -> smem
    {
        const uint4* src = reinterpret_cast<const uint4*>(g_h16 + (size_t)b * N_ * D_);
        uint4* dst = reinterpret_cast<uint4*>(smem_raw);
#pragma unroll
        for (int s = 0; s < 8; s++)
            dst[threadIdx.x + s * 512] = src[threadIdx.x + s * 512];
    }
    __syncthreads();

    const int* arow = (dir ? g_adjT : adj) + (size_t)row * N_;
    short* list = lst + wl * N_;
    unsigned lt = (1u << lane) - 1u;

    // load adj row into registers (coalesced int4)
    int4 av[4];
#pragma unroll
    for (int c = 0; c < 4; c++)
        av[c] = reinterpret_cast<const int4*>(arow)[c * 32 + lane];

    // pass 1: histogram via ballots
    int cnt[8] = {0, 0, 0, 0, 0, 0, 0, 0};
#pragma unroll
    for (int c = 0; c < 4; c++) {
        int vals[4] = {av[c].x, av[c].y, av[c].z, av[c].w};
#pragma unroll
        for (int u = 0; u < 4; u++) {
            int kv = vals[u];
#pragma unroll
            for (int k = 1; k <= 8; k++)
                cnt[k - 1] += __popc(__ballot_sync(0xffffffffu, kv == k));
        }
    }
    int offs[9];
    offs[0] = 0;
#pragma unroll
    for (int k = 0; k < 8; k++) offs[k + 1] = offs[k] + cnt[k];

    // pass 2: scatter j-indices into bucket segments
    int base[8];
#pragma unroll
    for (int k = 0; k < 8; k++) base[k] = offs[k];
#pragma unroll
    for (int c = 0; c < 4; c++) {
        int vals[4] = {av[c].x, av[c].y, av[c].z, av[c].w};
#pragma unroll
        for (int u = 0; u < 4; u++) {
            int kv  = vals[u];
            int jj  = c * 128 + lane * 4 + u;
            int pos = 0;
#pragma unroll
            for (int k = 1; k <= 8; k++) {
                unsigned m = __ballot_sync(0xffffffffu, kv == k);
                if (kv == k) pos = base[k - 1] + __popc(m & lt);
                base[k - 1] += __popc(m);
            }
            if (kv) list[pos] = (short)jj;
        }
    }
    __syncwarp();

    // pass 3: per-bucket register accumulation from smem fp16 tile
    float* So = &g_S[dir][(size_t)row * SKD_];
#pragma unroll
    for (int k = 0; k < 8; k++) {
        float2 a0 = make_float2(0.f, 0.f), a1 = a0, a2 = a0, a3 = a0;
        int idx = offs[k];
        int end = offs[k + 1];
        for (; idx + 4 <= end; idx += 4) {
            int j0 = list[idx], j1 = list[idx + 1], j2 = list[idx + 2], j3 = list[idx + 3];
            float2 v0 = __half22float2(h2[j0 * 32 + lane]);
            float2 v1 = __half22float2(h2[j1 * 32 + lane]);
            float2 v2 = __half22float2(h2[j2 * 32 + lane]);
            float2 v3 = __half22float2(h2[j3 * 32 + lane]);
            a0.x += v0.x; a0.y += v0.y;
            a1.x += v1.x; a1.y += v1.y;
            a2.x += v2.x; a2.y += v2.y;
            a3.x += v3.x; a3.y += v3.y;
        }
        for (; idx < end; idx++) {
            float2 v0 = __half22float2(h2[list[idx] * 32 + lane]);
            a0.x += v0.x; a0.y += v0.y;
        }
        float2 s;
        s.x = (a0.x + a1.x) + (a2.x + a3.x);
        s.y = (a0.y + a1.y) + (a2.y + a3.y);
        *reinterpret_cast<float2*>(&So[k * D_ + 2 * lane]) = s;
    }
}

// ---------------- kernel 4: GEMM + bias (8x4 tiles, FFMA2) ----------------
#define BM 64
#define BN 64
#define BK 32
__global__ __launch_bounds__(128)
void gemm_out(const float* __restrict__ bias, float* __restrict__ out) {
    int dir = blockIdx.y;
    const float* Sd = g_S[dir];
    const float* Wd = g_W[dir];

    __shared__ float As[BK][BM + 4];   // +4 keeps 16B alignment per row
    __shared__ float Bs[BK][BN];

    int tid  = threadIdx.x;            // 128 threads
    int tx   = tid & 15;               // n: 4 per thread
    int ty   = tid >> 4;               // m: 8 per thread (0..7)
    int row0 = blockIdx.x * BM;

    unsigned long long acc2[4][4];     // [m-pair][n]
#pragma unroll
    for (int mp = 0; mp < 4; mp++)
#pragma unroll
        for (int n = 0; n < 4; n++) acc2[mp][n] = 0ull;

    for (int kk = 0; kk < SKD_; kk += BK) {
        // load A tile 64x32 (transposed into As[k][m]): 4 float4 per thread
#pragma unroll
        for (int l = 0; l < 4; l++) {
            int idx = tid + l * 128;          // 0..511
            int m   = idx >> 3;
            int k4  = (idx & 7) * 4;
            float4 v = *reinterpret_cast<const float4*>(
                &Sd[(size_t)(row0 + m) * SKD_ + kk + k4]);
            As[k4 + 0][m] = v.x;
            As[k4 + 1][m] = v.y;
            As[k4 + 2][m] = v.z;
            As[k4 + 3][m] = v.w;
        }
        // load B tile 32x64: 4 float4 per thread
#pragma unroll
        for (int l = 0; l < 4; l++) {
            int idx = tid + l * 128;
            int k   = idx >> 4;
            int n4  = (idx & 15) * 4;
            *reinterpret_cast<float4*>(&Bs[k][n4]) =
                *reinterpret_cast<const float4*>(&Wd[(size_t)(kk + k) * D_ + n4]);
        }
        __syncthreads();
#pragma unroll
        for (int k = 0; k < BK; k++) {
            // a-pairs: 8 m values = 4 packed pairs, natively contiguous
            const unsigned long long* ap =
                reinterpret_cast<const unsigned long long*>(&As[k][ty * 8]);
            unsigned long long a0 = ap[0], a1 = ap[1], a2 = ap[2], a3 = ap[3];
            float4 bf = *reinterpret_cast<const float4*>(&Bs[k][tx * 4]);
            unsigned long long b0 = pack2(bf.x, bf.x);
            unsigned long long b1 = pack2(bf.y, bf.y);
            unsigned long long b2 = pack2(bf.z, bf.z);
            unsigned long long b3 = pack2(bf.w, bf.w);
            fma2(acc2[0][0], a0, b0); fma2(acc2[0][1], a0, b1);
            fma2(acc2[0][2], a0, b2); fma2(acc2[0][3], a0, b3);
            fma2(acc2[1][0], a1, b0); fma2(acc2[1][1], a1, b1);
            fma2(acc2[1][2], a1, b2); fma2(acc2[1][3], a1, b3);
            fma2(acc2[2][0], a2, b0); fma2(acc2[2][1], a2, b1);
            fma2(acc2[2][2], a2, b2); fma2(acc2[2][3], a2, b3);
            fma2(acc2[3][0], a3, b0); fma2(acc2[3][1], a3, b1);
            fma2(acc2[3][2], a3, b2); fma2(acc2[3][3], a3, b3);
        }
        __syncthreads();
    }

    int n = tx * 4;
    float4 bv = *reinterpret_cast<const float4*>(&bias[dir * 64 + n]);
#pragma unroll
    for (int mp = 0; mp < 4; mp++) {
        float lo[4], hi[4];
#pragma unroll
        for (int j = 0; j < 4; j++) unpack2(acc2[mp][j], lo[j], hi[j]);
        int m = row0 + ty * 8 + mp * 2;
        float4 o0, o1;
        o0.x = lo[0] + bv.x; o0.y = lo[1] + bv.y; o0.z = lo[2] + bv.z; o0.w = lo[3] + bv.w;
        o1.x = hi[0] + bv.x; o1.y = hi[1] + bv.y; o1.z = hi[2] + bv.z; o1.w = hi[3] + bv.w;
        *reinterpret_cast<float4*>(&out[(size_t)m * 128 + dir * 64 + n])       = o0;
        *reinterpret_cast<float4*>(&out[(size_t)(m + 1) * 128 + dir * 64 + n]) = o1;
    }
}

// ---------------- launch ----------------------------------------------------
extern "C" void kernel_launch(void* const* d_in, const int* in_sizes, int n_in,
                              void* d_out, int out_size) {
    const float* h     = (const float*)d_in[0];   // [16,512,64]
    const int*   adj   = (const int*)d_in[1];     // [16,512,512]
    const float* min_  = (const float*)d_in[3];   // [8,64,64]
    const float* mout_ = (const float*)d_in[4];   // [8,64,64]
    const float* bias  = (const float*)d_in[5];   // [128]
    float* out = (float*)d_out;                   // [16,512,128]

    static int smem_set = 0;
    const int AGG_SMEM = N_ * D_ * 2 + 16 * N_ * 2;   // 64KB h16 + 16KB lists = 80KB
    if (!smem_set) {
        cudaFuncSetAttribute(aggregate, cudaFuncAttributeMaxDynamicSharedMemorySize, AGG_SMEM);
        smem_set = 1;
    }

    transpose_adj<<<dim3(16, 16, 16), dim3(32, 8)>>>(adj);
    wprep<<<256, 256>>>(min_, mout_);
    hprep<<<1024, 256>>>(h);
    aggregate<<<1024, 512, AGG_SMEM>>>(adj);      // 16384 warps = 8192 rows x 2 dirs
    gemm_out<<<dim3(128, 2), 128>>>(bias, out);
}

// round 5
// speedup vs baseline: 5.0175x; 3.6729x over previous
#include <cuda_runtime.h>
#include <cuda_fp16.h>
#include <cstdint>

#define B_ 16
#define N_ 512
#define D_ 64
#define K_ 8

// ---------------- static device scratch -----------------------------------
__device__ __align__(16) __half g_hT16[B_ * D_ * N_];    // [b][e][j]  1 MB
__device__ __align__(16) __half g_Wh[2][K_ * D_ * D_];   // [dir][k][n][e] 128 KB

// pitches (in elements)
#define HT_PITCH  520    // halves per e-row       (conflict-free LDS.32 frags)
#define WS_PITCH  72     // halves per (k,n)-row   (conflict-free LDS.32 frags)
#define ADJ_PITCH 72     // ints  per i-row        (conflict-free LDS.64 frags)
#define SRED_PITCH 66    // floats per i-row

// smem byte layout
#define OFF_HT   0
#define SZ_SRED  (8 * 32 * SRED_PITCH * 4)       // 67584 (overlays hT region)
#define OFF_WS   67584
#define SZ_WS    (K_ * D_ * WS_PITCH * 2)        // 73728
#define OFF_ADJ  (OFF_WS + SZ_WS)                // 141312
#define SZ_ADJ   (32 * ADJ_PITCH * 4)            // 9216
#define SB_SMEM  (OFF_ADJ + SZ_ADJ)              // 150528

// ---------------- mma.sync m16n8k16 f16->f32 -------------------------------
__device__ __forceinline__ void mma16816(float* d,
                                         uint32_t a0, uint32_t a1, uint32_t a2, uint32_t a3,
                                         uint32_t b0, uint32_t b1) {
    asm volatile(
        "mma.sync.aligned.m16n8k16.row.col.f32.f16.f16.f32 "
        "{%0,%1,%2,%3}, {%4,%5,%6,%7}, {%8,%9}, {%0,%1,%2,%3};"
        : "+f"(d[0]), "+f"(d[1]), "+f"(d[2]), "+f"(d[3])
        : "r"(a0), "r"(a1), "r"(a2), "r"(a3), "r"(b0), "r"(b1));
}

// one-hot pack: two adj ints -> packed fp16x2 (1.0 where ==k)
__device__ __forceinline__ uint32_t onehot2(int vx, int vy, int k) {
    uint32_t lo = (vx == k) ? 0x3C00u : 0u;
    uint32_t hi = (vy == k) ? 0x3C00u : 0u;
    return lo | (hi << 16);
}

__device__ __forceinline__ uint32_t packh2(float x, float y) {
    __half2 h = __floats2half2_rn(x, y);
    return *reinterpret_cast<uint32_t*>(&h);
}

// ---------------- kernel 1: hT prep  (fp32 [b][j][e] -> fp16 [b][e][j]) ----
__global__ void hTprep(const float* __restrict__ h) {
    __shared__ float tile[32][33];
    int j0 = blockIdx.x * 32;
    int e0 = blockIdx.y * 32;
    int b  = blockIdx.z;
    int tx = threadIdx.x, ty = threadIdx.y;  // 32 x 8
#pragma unroll
    for (int r = 0; r < 32; r += 8)
        tile[ty + r][tx] = h[((size_t)b * N_ + j0 + ty + r) * D_ + e0 + tx];
    __syncthreads();
#pragma unroll
    for (int r = 0; r < 32; r += 8)
        g_hT16[((size_t)b * D_ + e0 + ty + r) * N_ + j0 + tx] =
            __float2half_rn(tile[tx][ty + r]);
}

// ---------------- kernel 2: W prep (fp32 -> fp16, same layout) -------------
// g_Wh[dir][k][n][e] = mat_dir[k][n][e]   (Min is [k][d=n][e] row-major)
__global__ void wprep(const float* __restrict__ min_, const float* __restrict__ mout_) {
    int idx = blockIdx.x * 256 + threadIdx.x;   // 0..65535
    int dir = idx >> 15;
    int r   = idx & 32767;
    g_Wh[dir][r] = __float2half_rn((dir ? mout_ : min_)[r]);
}

// ---------------- kernel 3: fused one-hot HMMA + weight GEMM --------------
// CTA = (dir, b, 32-row i tile). Warp w handles edge type k = w+1.
__global__ __launch_bounds__(256, 1)
void fused(const int* __restrict__ adj, const float* __restrict__ bias,
           float* __restrict__ out) {
    extern __shared__ char sm[];
    __half* hts  = reinterpret_cast<__half*>(sm + OFF_HT);
    __half* wsm  = reinterpret_cast<__half*>(sm + OFF_WS);
    int*    ajs  = reinterpret_cast<int*>(sm + OFF_ADJ);
    float*  sred = reinterpret_cast<float*>(sm + OFF_HT);   // reuse after mainloop

    int tid = threadIdx.x, lane = tid & 31, w = tid >> 5;
    int job   = blockIdx.x;
    int itile = job & 15;
    int b     = (job >> 4) & 15;
    int dir   = job >> 8;
    int i0    = itile * 32;
    int kw    = w + 1;
    int t2    = (lane & 3) * 2;
    int g     = lane >> 2;

    const int* adjb = adj + (size_t)b * N_ * N_;

    // ---- cooperative loads: hT (64KB) + W[dir] (64KB) into smem ----------
    {
        const uint4* src = reinterpret_cast<const uint4*>(g_hT16 + (size_t)b * D_ * N_);
#pragma unroll
        for (int s = 0; s < 16; s++) {
            int gg = tid + s * 256;               // 4096 uint4
            int e = gg >> 6, c = gg & 63;
            *reinterpret_cast<uint4*>(reinterpret_cast<char*>(hts) + e * (HT_PITCH * 2) + c * 16) = src[gg];
        }
        const uint4* wsrc = reinterpret_cast<const uint4*>(g_Wh[dir]);
#pragma unroll
        for (int s = 0; s < 16; s++) {
            int gg  = tid + s * 256;              // 4096 uint4
            int row = gg >> 3, c = gg & 7;        // row = k*64+n (512 rows of 128B)
            *reinterpret_cast<uint4*>(reinterpret_cast<char*>(wsm) + row * (WS_PITCH * 2) + c * 16) = wsrc[gg];
        }
    }

    // ---- prefetch adj chunk 0 ---------------------------------------------
    int4 p0, p1;
    {
        if (dir == 0) {
            int row = tid >> 3, cb = (tid & 7) * 8;
            const int* s = &adjb[(size_t)(i0 + row) * N_ + cb];
            p0 = *reinterpret_cast<const int4*>(s);
            p1 = *reinterpret_cast<const int4*>(s + 4);
        } else {
            int jr = tid >> 2, ib = (tid & 3) * 8;
            const int* s = &adjb[(size_t)jr * N_ + i0 + ib];
            p0 = *reinterpret_cast<const int4*>(s);
            p1 = *reinterpret_cast<const int4*>(s + 4);
        }
    }

    float acc[2][8][4];
#pragma unroll
    for (int ig = 0; ig < 2; ig++)
#pragma unroll
        for (int ng = 0; ng < 8; ng++)
#pragma unroll
            for (int q = 0; q < 4; q++) acc[ig][ng][q] = 0.f;

    // ---- main loop: 8 chunks of 64 j --------------------------------------
    for (int c = 0; c < 8; c++) {
        // store staged adj regs to smem (transposed for dir=1)
        if (dir == 0) {
            int row = tid >> 3, cb = (tid & 7) * 8;
            int* d = &ajs[row * ADJ_PITCH + cb];
            *reinterpret_cast<int4*>(d)     = p0;
            *reinterpret_cast<int4*>(d + 4) = p1;
        } else {
            int jr = tid >> 2, ib = (tid & 3) * 8;
            ajs[(ib + 0) * ADJ_PITCH + jr] = p0.x;
            ajs[(ib + 1) * ADJ_PITCH + jr] = p0.y;
            ajs[(ib + 2) * ADJ_PITCH + jr] = p0.z;
            ajs[(ib + 3) * ADJ_PITCH + jr] = p0.w;
            ajs[(ib + 4) * ADJ_PITCH + jr] = p1.x;
            ajs[(ib + 5) * ADJ_PITCH + jr] = p1.y;
            ajs[(ib + 6) * ADJ_PITCH + jr] = p1.z;
            ajs[(ib + 7) * ADJ_PITCH + jr] = p1.w;
        }
        __syncthreads();

        // prefetch next chunk (overlaps with the 4 sub-chunk computes)
        if (c < 7) {
            int j0n = (c + 1) * 64;
            if (dir == 0) {
                int row = tid >> 3, cb = (tid & 7) * 8;
                const int* s = &adjb[(size_t)(i0 + row) * N_ + j0n + cb];
                p0 = *reinterpret_cast<const int4*>(s);
                p1 = *reinterpret_cast<const int4*>(s + 4);
            } else {
                int jr = tid >> 2, ib = (tid & 3) * 8;
                const int* s = &adjb[(size_t)(j0n + jr) * N_ + i0 + ib];
                p0 = *reinterpret_cast<const int4*>(s);
                p1 = *reinterpret_cast<const int4*>(s + 4);
            }
        }

#pragma unroll
        for (int js = 0; js < 4; js++) {
            int jb = c * 64 + js * 16;
            // B fragments: h pairs along j (half2), conflict-free
            uint32_t bb[8][2];
#pragma unroll
            for (int ng = 0; ng < 8; ng++) {
                const __half* hr = hts + (ng * 8 + g) * HT_PITCH + jb;
                bb[ng][0] = *reinterpret_cast<const uint32_t*>(hr + t2);
                bb[ng][1] = *reinterpret_cast<const uint32_t*>(hr + t2 + 8);
            }
#pragma unroll
            for (int ig = 0; ig < 2; ig++) {
                const int* ap  = ajs + (ig * 16 + g) * ADJ_PITCH + js * 16;
                const int* ap8 = ap + 8 * ADJ_PITCH;
                int2 v00 = *reinterpret_cast<const int2*>(ap + t2);
                int2 v10 = *reinterpret_cast<const int2*>(ap8 + t2);
                int2 v01 = *reinterpret_cast<const int2*>(ap + t2 + 8);
                int2 v11 = *reinterpret_cast<const int2*>(ap8 + t2 + 8);
                uint32_t a0 = onehot2(v00.x, v00.y, kw);
                uint32_t a1 = onehot2(v10.x, v10.y, kw);
                uint32_t a2 = onehot2(v01.x, v01.y, kw);
                uint32_t a3 = onehot2(v11.x, v11.y, kw);
#pragma unroll
                for (int ng = 0; ng < 8; ng++)
                    mma16816(acc[ig][ng], a0, a1, a2, a3, bb[ng][0], bb[ng][1]);
            }
        }
        __syncthreads();
    }

    // ---- fused epilogue: P[i][n] = sum_e S[i][e] * W[k][n][e] -------------
    float oacc[2][8][4];
#pragma unroll
    for (int ig = 0; ig < 2; ig++)
#pragma unroll
        for (int ng = 0; ng < 8; ng++)
#pragma unroll
            for (int q = 0; q < 4; q++) oacc[ig][ng][q] = 0.f;

    const __half* wk = wsm + (size_t)w * 64 * WS_PITCH;
#pragma unroll
    for (int ig = 0; ig < 2; ig++) {
#pragma unroll
        for (int dc = 0; dc < 4; dc++) {
            const float* cA = acc[ig][2 * dc];
            const float* cB = acc[ig][2 * dc + 1];
            // hi fragments (fp16 of S), lo fragments (exact residual)
            uint32_t ah0 = packh2(cA[0], cA[1]);
            uint32_t ah1 = packh2(cA[2], cA[3]);
            uint32_t ah2 = packh2(cB[0], cB[1]);
            uint32_t ah3 = packh2(cB[2], cB[3]);
            float r0 = cA[0] - __half2float(__ushort_as_half((unsigned short)(ah0 & 0xFFFF)));
            float r1 = cA[1] - __half2float(__ushort_as_half((unsigned short)(ah0 >> 16)));
            float r2 = cA[2] - __half2float(__ushort_as_half((unsigned short)(ah1 & 0xFFFF)));
            float r3 = cA[3] - __half2float(__ushort_as_half((unsigned short)(ah1 >> 16)));
            float r4 = cB[0] - __half2float(__ushort_as_half((unsigned short)(ah2 & 0xFFFF)));
            float r5 = cB[1] - __half2float(__ushort_as_half((unsigned short)(ah2 >> 16)));
            float r6 = cB[2] - __half2float(__ushort_as_half((unsigned short)(ah3 & 0xFFFF)));
            float r7 = cB[3] - __half2float(__ushort_as_half((unsigned short)(ah3 >> 16)));
            uint32_t al0 = packh2(r0, r1);
            uint32_t al1 = packh2(r2, r3);
            uint32_t al2 = packh2(r4, r5);
            uint32_t al3 = packh2(r6, r7);
#pragma unroll
            for (int ng = 0; ng < 8; ng++) {
                const __half* wr = wk + (ng * 8 + g) * WS_PITCH + dc * 16;
                uint32_t b0 = *reinterpret_cast<const uint32_t*>(wr + t2);
                uint32_t b1 = *reinterpret_cast<const uint32_t*>(wr + t2 + 8);
                mma16816(oacc[ig][ng], ah0, ah1, ah2, ah3, b0, b1);
                mma16816(oacc[ig][ng], al0, al1, al2, al3, b0, b1);
            }
        }
    }

    // ---- cross-k reduction via smem (reuse hT region) ----------------------
    float* sr = sred + (size_t)w * 32 * SRED_PITCH;
#pragma unroll
    for (int ig = 0; ig < 2; ig++)
#pragma unroll
        for (int ng = 0; ng < 8; ng++) {
            float2 lo = make_float2(oacc[ig][ng][0], oacc[ig][ng][1]);
            float2 hi = make_float2(oacc[ig][ng][2], oacc[ig][ng][3]);
            *reinterpret_cast<float2*>(&sr[(ig * 16 + g) * SRED_PITCH + ng * 8 + t2])     = lo;
            *reinterpret_cast<float2*>(&sr[(ig * 16 + g + 8) * SRED_PITCH + ng * 8 + t2]) = hi;
        }
    __syncthreads();

    // ---- final sum over 8 warps + bias + store -----------------------------
    {
        int r  = tid >> 3;            // 0..31 (i row)
        int nb = (tid & 7) * 8;       // 0..56 (n col base)
        float s[8];
#pragma unroll
        for (int u = 0; u < 8; u++) s[u] = 0.f;
#pragma unroll
        for (int ww = 0; ww < 8; ww++) {
            const float* p = sred + (size_t)(ww * 32 + r) * SRED_PITCH + nb;
#pragma unroll
            for (int u = 0; u < 8; u++) s[u] += p[u];
        }
        const float* bp = bias + dir * 64 + nb;
        float* op = &out[(size_t)((b * N_) + i0 + r) * 128 + dir * 64 + nb];
        float4 o0, o1;
        o0.x = s[0] + bp[0]; o0.y = s[1] + bp[1]; o0.z = s[2] + bp[2]; o0.w = s[3] + bp[3];
        o1.x = s[4] + bp[4]; o1.y = s[5] + bp[5]; o1.z = s[6] + bp[6]; o1.w = s[7] + bp[7];
        *reinterpret_cast<float4*>(op)     = o0;
        *reinterpret_cast<float4*>(op + 4) = o1;
    }
}

// ---------------- launch ----------------------------------------------------
extern "C" void kernel_launch(void* const* d_in, const int* in_sizes, int n_in,
                              void* d_out, int out_size) {
    const float* h     = (const float*)d_in[0];   // [16,512,64]
    const int*   adj   = (const int*)d_in[1];     // [16,512,512]
    const float* min_  = (const float*)d_in[3];   // [8,64,64]
    const float* mout_ = (const float*)d_in[4];   // [8,64,64]
    const float* bias  = (const float*)d_in[5];   // [128]
    float* out = (float*)d_out;                   // [16,512,128]

    static int cfg = 0;
    if (!cfg) {
        cudaFuncSetAttribute(fused, cudaFuncAttributeMaxDynamicSharedMemorySize, SB_SMEM);
        cfg = 1;
    }

    hTprep<<<dim3(16, 2, 16), dim3(32, 8)>>>(h);
    wprep<<<256, 256>>>(min_, mout_);
    fused<<<512, 256, SB_SMEM>>>(adj, bias, out);  // 2 dir x 16 b x 16 itiles
}

// round 6
// speedup vs baseline: 5.0919x; 1.0148x over previous
#include <cuda_runtime.h>
#include <cuda_fp16.h>
#include <cstdint>

#define B_ 16
#define N_ 512
#define D_ 64
#define K_ 8

// ---------------- static device scratch -----------------------------------
__device__ __align__(16) __half g_hT16[B_ * D_ * N_];    // [b][e][j]  1 MB
__device__ __align__(16) __half g_Wh[2][K_ * D_ * D_];   // [dir][k][n][e] 128 KB

// pitches (in elements)
#define HT_PITCH  520    // halves per e-row   (bank = 4*eg + (lane&3): conflict-free)
#define ADJ_PITCH 72     // ints per i-row     (conflict-free LDS.64 frags)
#define SRED_PITCH 66    // floats per i-row

// smem byte layout (sred overlays hT after the main loop)
#define OFF_HT   0
#define SZ_HT    (D_ * HT_PITCH * 2)             // 66560
#define SZ_SRED  (8 * 32 * SRED_PITCH * 4)       // 67584
#define OFF_ADJ  67584
#define SZ_ADJ   (32 * ADJ_PITCH * 4)            // 9216
#define SB_SMEM  (OFF_ADJ + SZ_ADJ)              // 76800  -> 2 CTAs/SM

// ---------------- mma.sync m16n8k16 f16->f32 -------------------------------
__device__ __forceinline__ void mma16816(float* d,
                                         uint32_t a0, uint32_t a1, uint32_t a2, uint32_t a3,
                                         uint32_t b0, uint32_t b1) {
    asm volatile(
        "mma.sync.aligned.m16n8k16.row.col.f32.f16.f16.f32 "
        "{%0,%1,%2,%3}, {%4,%5,%6,%7}, {%8,%9}, {%0,%1,%2,%3};"
        : "+f"(d[0]), "+f"(d[1]), "+f"(d[2]), "+f"(d[3])
        : "r"(a0), "r"(a1), "r"(a2), "r"(a3), "r"(b0), "r"(b1));
}

__device__ __forceinline__ uint32_t onehot2(int vx, int vy, int k) {
    uint32_t lo = (vx == k) ? 0x3C00u : 0u;
    uint32_t hi = (vy == k) ? 0x3C00u : 0u;
    return lo | (hi << 16);
}

__device__ __forceinline__ uint32_t packh2(float x, float y) {
    __half2 h = __floats2half2_rn(x, y);
    return *reinterpret_cast<uint32_t*>(&h);
}

// ---------------- kernel 1: hT prep  (fp32 [b][j][e] -> fp16 [b][e][j]) ----
__global__ void hTprep(const float* __restrict__ h) {
    __shared__ float tile[32][33];
    int j0 = blockIdx.x * 32;
    int e0 = blockIdx.y * 32;
    int b  = blockIdx.z;
    int tx = threadIdx.x, ty = threadIdx.y;  // 32 x 8
#pragma unroll
    for (int r = 0; r < 32; r += 8)
        tile[ty + r][tx] = h[((size_t)b * N_ + j0 + ty + r) * D_ + e0 + tx];
    __syncthreads();
#pragma unroll
    for (int r = 0; r < 32; r += 8)
        g_hT16[((size_t)b * D_ + e0 + ty + r) * N_ + j0 + tx] =
            __float2half_rn(tile[tx][ty + r]);
}

// ---------------- kernel 2: W prep (fp32 -> fp16, same layout) -------------
__global__ void wprep(const float* __restrict__ min_, const float* __restrict__ mout_) {
    int idx = blockIdx.x * 256 + threadIdx.x;   // 0..65535
    int dir = idx >> 15;
    int r   = idx & 32767;
    g_Wh[dir][r] = __float2half_rn((dir ? mout_ : min_)[r]);
}

// ---------------- kernel 3: fused one-hot HMMA + weight GEMM --------------
// CTA = (dir, b, 32-row i tile). Warp w handles edge type k = w+1.
__global__ __launch_bounds__(256, 2)
void fused(const int* __restrict__ adj, const float* __restrict__ bias,
           float* __restrict__ out) {
    extern __shared__ char sm[];
    __half* hts  = reinterpret_cast<__half*>(sm + OFF_HT);
    int*    ajs  = reinterpret_cast<int*>(sm + OFF_ADJ);
    float*  sred = reinterpret_cast<float*>(sm + OFF_HT);   // reuse after mainloop

    int tid = threadIdx.x, lane = tid & 31, w = tid >> 5;
    int job   = blockIdx.x;
    int itile = job & 15;
    int b     = (job >> 4) & 15;
    int dir   = job >> 8;
    int i0    = itile * 32;
    int kw    = w + 1;
    int t2    = (lane & 3) * 2;
    int g     = lane >> 2;

    const int* adjb = adj + (size_t)b * N_ * N_;

    // ---- cooperative load: hT (64KB fp16) into smem ------------------------
    {
        const uint4* src = reinterpret_cast<const uint4*>(g_hT16 + (size_t)b * D_ * N_);
#pragma unroll
        for (int s = 0; s < 16; s++) {
            int gg = tid + s * 256;               // 4096 uint4
            int e = gg >> 6, c = gg & 63;
            *reinterpret_cast<uint4*>(reinterpret_cast<char*>(hts)
                                      + e * (HT_PITCH * 2) + c * 16) = src[gg];
        }
    }

    // ---- prefetch adj chunk 0 ----------------------------------------------
    int4 p0, p1;
    if (dir == 0) {
        int row = tid >> 3, cb = (tid & 7) * 8;
        const int* s = &adjb[(size_t)(i0 + row) * N_ + cb];
        p0 = *reinterpret_cast<const int4*>(s);
        p1 = *reinterpret_cast<const int4*>(s + 4);
    } else {
        int jr = tid >> 2, ib = (tid & 3) * 8;
        const int* s = &adjb[(size_t)jr * N_ + i0 + ib];
        p0 = *reinterpret_cast<const int4*>(s);
        p1 = *reinterpret_cast<const int4*>(s + 4);
    }

    float acc[2][8][4];
#pragma unroll
    for (int ig = 0; ig < 2; ig++)
#pragma unroll
        for (int ng = 0; ng < 8; ng++)
#pragma unroll
            for (int q = 0; q < 4; q++) acc[ig][ng][q] = 0.f;

    // ---- main loop: 8 chunks of 64 j ---------------------------------------
    for (int c = 0; c < 8; c++) {
        if (dir == 0) {
            int row = tid >> 3, cb = (tid & 7) * 8;
            int* d = &ajs[row * ADJ_PITCH + cb];
            *reinterpret_cast<int4*>(d)     = p0;
            *reinterpret_cast<int4*>(d + 4) = p1;
        } else {
            int jr = tid >> 2, ib = (tid & 3) * 8;
            ajs[(ib + 0) * ADJ_PITCH + jr] = p0.x;
            ajs[(ib + 1) * ADJ_PITCH + jr] = p0.y;
            ajs[(ib + 2) * ADJ_PITCH + jr] = p0.z;
            ajs[(ib + 3) * ADJ_PITCH + jr] = p0.w;
            ajs[(ib + 4) * ADJ_PITCH + jr] = p1.x;
            ajs[(ib + 5) * ADJ_PITCH + jr] = p1.y;
            ajs[(ib + 6) * ADJ_PITCH + jr] = p1.z;
            ajs[(ib + 7) * ADJ_PITCH + jr] = p1.w;
        }
        __syncthreads();

        if (c < 7) {
            int j0n = (c + 1) * 64;
            if (dir == 0) {
                int row = tid >> 3, cb = (tid & 7) * 8;
                const int* s = &adjb[(size_t)(i0 + row) * N_ + j0n + cb];
                p0 = *reinterpret_cast<const int4*>(s);
                p1 = *reinterpret_cast<const int4*>(s + 4);
            } else {
                int jr = tid >> 2, ib = (tid & 3) * 8;
                const int* s = &adjb[(size_t)(j0n + jr) * N_ + i0 + ib];
                p0 = *reinterpret_cast<const int4*>(s);
                p1 = *reinterpret_cast<const int4*>(s + 4);
            }
        }

#pragma unroll
        for (int js = 0; js < 4; js++) {
            int jb = c * 64 + js * 16;
            uint32_t bb[8][2];
#pragma unroll
            for (int ng = 0; ng < 8; ng++) {
                const __half* hr = hts + (ng * 8 + g) * HT_PITCH + jb;
                bb[ng][0] = *reinterpret_cast<const uint32_t*>(hr + t2);
                bb[ng][1] = *reinterpret_cast<const uint32_t*>(hr + t2 + 8);
            }
#pragma unroll
            for (int ig = 0; ig < 2; ig++) {
                const int* ap  = ajs + (ig * 16 + g) * ADJ_PITCH + js * 16;
                const int* ap8 = ap + 8 * ADJ_PITCH;
                int2 v00 = *reinterpret_cast<const int2*>(ap + t2);
                int2 v10 = *reinterpret_cast<const int2*>(ap8 + t2);
                int2 v01 = *reinterpret_cast<const int2*>(ap + t2 + 8);
                int2 v11 = *reinterpret_cast<const int2*>(ap8 + t2 + 8);
                uint32_t a0 = onehot2(v00.x, v00.y, kw);
                uint32_t a1 = onehot2(v10.x, v10.y, kw);
                uint32_t a2 = onehot2(v01.x, v01.y, kw);
                uint32_t a3 = onehot2(v11.x, v11.y, kw);
#pragma unroll
                for (int ng = 0; ng < 8; ng++)
                    mma16816(acc[ig][ng], a0, a1, a2, a3, bb[ng][0], bb[ng][1]);
            }
        }
        __syncthreads();
    }

    // ---- fused epilogue: P[i][n] = sum_e S[i][e] * W[k][n][e] --------------
    // W fragments streamed from gmem (L1-resident, 8 KB per warp's k).
    float oacc[2][8][4];
#pragma unroll
    for (int ig = 0; ig < 2; ig++)
#pragma unroll
        for (int ng = 0; ng < 8; ng++)
#pragma unroll
            for (int q = 0; q < 4; q++) oacc[ig][ng][q] = 0.f;

    const __half* wg = g_Wh[dir] + (size_t)w * D_ * D_;   // [64 n][64 e]
#pragma unroll
    for (int dc = 0; dc < 4; dc++) {
        uint32_t ah[2][4];
#pragma unroll
        for (int ig = 0; ig < 2; ig++) {
            const float* cA = acc[ig][2 * dc];
            const float* cB = acc[ig][2 * dc + 1];
            ah[ig][0] = packh2(cA[0], cA[1]);
            ah[ig][1] = packh2(cA[2], cA[3]);
            ah[ig][2] = packh2(cB[0], cB[1]);
            ah[ig][3] = packh2(cB[2], cB[3]);
        }
#pragma unroll
        for (int ng = 0; ng < 8; ng++) {
            const __half* wr = wg + (ng * 8 + g) * D_ + dc * 16;
            uint32_t b0 = *reinterpret_cast<const uint32_t*>(wr + t2);
            uint32_t b1 = *reinterpret_cast<const uint32_t*>(wr + t2 + 8);
            mma16816(oacc[0][ng], ah[0][0], ah[0][1], ah[0][2], ah[0][3], b0, b1);
            mma16816(oacc[1][ng], ah[1][0], ah[1][1], ah[1][2], ah[1][3], b0, b1);
        }
    }

    // ---- cross-k reduction via smem (reuse hT region) ----------------------
    float* sr = sred + (size_t)w * 32 * SRED_PITCH;
#pragma unroll
    for (int ig = 0; ig < 2; ig++)
#pragma unroll
        for (int ng = 0; ng < 8; ng++) {
            float2 lo = make_float2(oacc[ig][ng][0], oacc[ig][ng][1]);
            float2 hi = make_float2(oacc[ig][ng][2], oacc[ig][ng][3]);
            *reinterpret_cast<float2*>(&sr[(ig * 16 + g) * SRED_PITCH + ng * 8 + t2])     = lo;
            *reinterpret_cast<float2*>(&sr[(ig * 16 + g + 8) * SRED_PITCH + ng * 8 + t2]) = hi;
        }
    __syncthreads();

    // ---- final sum over 8 warps + bias + store ------------------------------
    {
        int r  = tid >> 3;            // 0..31 (i row)
        int nb = (tid & 7) * 8;       // 0..56 (n col base)
        float s[8];
#pragma unroll
        for (int u = 0; u < 8; u++) s[u] = 0.f;
#pragma unroll
        for (int ww = 0; ww < 8; ww++) {
            const float* p = sred + (size_t)(ww * 32 + r) * SRED_PITCH + nb;
#pragma unroll
            for (int u = 0; u < 8; u++) s[u] += p[u];
        }
        const float* bp = bias + dir * 64 + nb;
        float* op = &out[(size_t)((b * N_) + i0 + r) * 128 + dir * 64 + nb];
        float4 o0, o1;
        o0.x = s[0] + bp[0]; o0.y = s[1] + bp[1]; o0.z = s[2] + bp[2]; o0.w = s[3] + bp[3];
        o1.x = s[4] + bp[4]; o1.y = s[5] + bp[5]; o1.z = s[6] + bp[6]; o1.w = s[7] + bp[7];
        *reinterpret_cast<float4*>(op)     = o0;
        *reinterpret_cast<float4*>(op + 4) = o1;
    }
}

// ---------------- launch ----------------------------------------------------
extern "C" void kernel_launch(void* const* d_in, const int* in_sizes, int n_in,
                              void* d_out, int out_size) {
    const float* h     = (const float*)d_in[0];   // [16,512,64]
    const int*   adj   = (const int*)d_in[1];     // [16,512,512]
    const float* min_  = (const float*)d_in[3];   // [8,64,64]
    const float* mout_ = (const float*)d_in[4];   // [8,64,64]
    const float* bias  = (const float*)d_in[5];   // [128]
    float* out = (float*)d_out;                   // [16,512,128]

    static int cfg = 0;
    if (!cfg) {
        cudaFuncSetAttribute(fused, cudaFuncAttributeMaxDynamicSharedMemorySize, SB_SMEM);
        cfg = 1;
    }

    hTprep<<<dim3(16, 2, 16), dim3(32, 8)>>>(h);
    wprep<<<256, 256>>>(min_, mout_);
    fused<<<512, 256, SB_SMEM>>>(adj, bias, out);  // 2 dir x 16 b x 16 itiles
}

// round 7
// speedup vs baseline: 5.1561x; 1.0126x over previous
#include <cuda_runtime.h>
#include <cuda_fp16.h>
#include <cstdint>

#define B_ 16
#define N_ 512
#define D_ 64
#define K_ 8

// ---------------- static device scratch -----------------------------------
__device__ __align__(16) __half g_hT16[B_ * D_ * N_];    // [b][e][j]  1 MB
__device__ __align__(16) __half g_Wh[2][K_ * D_ * D_];   // [dir][k][n][e] 128 KB

// pitches (in elements)
#define HT_PITCH  520    // halves per e-row (conflict-free LDS.32 frags)
#define ADJ_PITCH 72     // ints per i-row   (conflict-free LDS.64 frags)
#define SRED_PITCH 66    // floats per i-row

// smem byte layout (sred overlays hT after the main loop)
#define OFF_HT   0
#define SZ_HT    (D_ * HT_PITCH * 2)             // 66560
#define SZ_SRED  (8 * 32 * SRED_PITCH * 4)       // 67584
#define OFF_ADJ  67584
#define SZ_ADJ   (32 * ADJ_PITCH * 4)            // 9216 (x2 buffers)
#define SB_SMEM  (OFF_ADJ + 2 * SZ_ADJ)          // 86016 -> 2 CTAs/SM

// ---------------- mma.sync m16n8k16 f16->f32 -------------------------------
__device__ __forceinline__ void mma16816(float* d,
                                         uint32_t a0, uint32_t a1, uint32_t a2, uint32_t a3,
                                         uint32_t b0, uint32_t b1) {
    asm volatile(
        "mma.sync.aligned.m16n8k16.row.col.f32.f16.f16.f32 "
        "{%0,%1,%2,%3}, {%4,%5,%6,%7}, {%8,%9}, {%0,%1,%2,%3};"
        : "+f"(d[0]), "+f"(d[1]), "+f"(d[2]), "+f"(d[3])
        : "r"(a0), "r"(a1), "r"(a2), "r"(a3), "r"(b0), "r"(b1));
}

__device__ __forceinline__ uint32_t onehot2(int vx, int vy, int k) {
    uint32_t lo = (vx == k) ? 0x3C00u : 0u;
    uint32_t hi = (vy == k) ? 0x3C00u : 0u;
    return lo | (hi << 16);
}

__device__ __forceinline__ uint32_t packh2(float x, float y) {
    __half2 h = __floats2half2_rn(x, y);
    return *reinterpret_cast<uint32_t*>(&h);
}

// ---------------- kernel 1: prep (hT fp16 transpose + W fp16) --------------
__global__ void prep(const float* __restrict__ h,
                     const float* __restrict__ min_, const float* __restrict__ mout_) {
    int bid = blockIdx.x;
    int tx = threadIdx.x, ty = threadIdx.y;        // 32 x 8
    if (bid < 512) {
        __shared__ float tile[32][33];
        int j0 = (bid & 15) * 32;
        int e0 = ((bid >> 4) & 1) * 32;
        int b  = bid >> 5;
#pragma unroll
        for (int r = 0; r < 32; r += 8)
            tile[ty + r][tx] = h[((size_t)b * N_ + j0 + ty + r) * D_ + e0 + tx];
        __syncthreads();
#pragma unroll
        for (int r = 0; r < 32; r += 8)
            g_hT16[((size_t)b * D_ + e0 + ty + r) * N_ + j0 + tx] =
                __float2half_rn(tile[tx][ty + r]);
    } else {
        int idx = (bid - 512) * 256 + ty * 32 + tx;  // 0..65535
        int dir = idx >> 15;
        int r   = idx & 32767;
        g_Wh[dir][r] = __float2half_rn((dir ? mout_ : min_)[r]);
    }
}

// ---------------- kernel 2: fused one-hot HMMA + weight GEMM --------------
// CTA = (dir, b, 32-row i tile). Warp w handles edge type k = w+1.
__global__ __launch_bounds__(256, 2)
void fused(const int* __restrict__ adj, const float* __restrict__ bias,
           float* __restrict__ out) {
    extern __shared__ char sm[];
    __half* hts  = reinterpret_cast<__half*>(sm + OFF_HT);
    float*  sred = reinterpret_cast<float*>(sm + OFF_HT);   // reuse after mainloop

    int tid = threadIdx.x, lane = tid & 31, w = tid >> 5;
    int job   = blockIdx.x;
    int itile = job & 15;
    int b     = (job >> 4) & 15;
    int dir   = job >> 8;
    int i0    = itile * 32;
    int kw    = w + 1;
    int t2    = (lane & 3) * 2;
    int g     = lane >> 2;

    const int* adjb = adj + (size_t)b * N_ * N_;

    // ---- cooperative load: hT (64KB fp16) into smem ------------------------
    {
        const uint4* src = reinterpret_cast<const uint4*>(g_hT16 + (size_t)b * D_ * N_);
#pragma unroll
        for (int s = 0; s < 16; s++) {
            int gg = tid + s * 256;               // 4096 uint4
            int e = gg >> 6, c = gg & 63;
            *reinterpret_cast<uint4*>(reinterpret_cast<char*>(hts)
                                      + e * (HT_PITCH * 2) + c * 16) = src[gg];
        }
    }

    // ---- prefetch adj chunk 0 ----------------------------------------------
    int4 p0, p1;
    if (dir == 0) {
        int row = tid >> 3, cb = (tid & 7) * 8;
        const int* s = &adjb[(size_t)(i0 + row) * N_ + cb];
        p0 = *reinterpret_cast<const int4*>(s);
        p1 = *reinterpret_cast<const int4*>(s + 4);
    } else {
        int jr = tid >> 2, ib = (tid & 3) * 8;
        const int* s = &adjb[(size_t)jr * N_ + i0 + ib];
        p0 = *reinterpret_cast<const int4*>(s);
        p1 = *reinterpret_cast<const int4*>(s + 4);
    }

    float acc[2][8][4];
#pragma unroll
    for (int ig = 0; ig < 2; ig++)
#pragma unroll
        for (int ng = 0; ng < 8; ng++)
#pragma unroll
            for (int q = 0; q < 4; q++) acc[ig][ng][q] = 0.f;

    // ---- main loop: 8 chunks of 64 j, double-buffered adj ------------------
    for (int c = 0; c < 8; c++) {
        int* abuf = reinterpret_cast<int*>(sm + OFF_ADJ + (c & 1) * SZ_ADJ);
        if (dir == 0) {
            int row = tid >> 3, cb = (tid & 7) * 8;
            int* d = &abuf[row * ADJ_PITCH + cb];
            *reinterpret_cast<int4*>(d)     = p0;
            *reinterpret_cast<int4*>(d + 4) = p1;
        } else {
            int jr = tid >> 2, ib = (tid & 3) * 8;
            abuf[(ib + 0) * ADJ_PITCH + jr] = p0.x;
            abuf[(ib + 1) * ADJ_PITCH + jr] = p0.y;
            abuf[(ib + 2) * ADJ_PITCH + jr] = p0.z;
            abuf[(ib + 3) * ADJ_PITCH + jr] = p0.w;
            abuf[(ib + 4) * ADJ_PITCH + jr] = p1.x;
            abuf[(ib + 5) * ADJ_PITCH + jr] = p1.y;
            abuf[(ib + 6) * ADJ_PITCH + jr] = p1.z;
            abuf[(ib + 7) * ADJ_PITCH + jr] = p1.w;
        }
        __syncthreads();

        if (c < 7) {
            int j0n = (c + 1) * 64;
            if (dir == 0) {
                int row = tid >> 3, cb = (tid & 7) * 8;
                const int* s = &adjb[(size_t)(i0 + row) * N_ + j0n + cb];
                p0 = *reinterpret_cast<const int4*>(s);
                p1 = *reinterpret_cast<const int4*>(s + 4);
            } else {
                int jr = tid >> 2, ib = (tid & 3) * 8;
                const int* s = &adjb[(size_t)(j0n + jr) * N_ + i0 + ib];
                p0 = *reinterpret_cast<const int4*>(s);
                p1 = *reinterpret_cast<const int4*>(s + 4);
            }
        }

#pragma unroll
        for (int js = 0; js < 4; js++) {
            int jb = c * 64 + js * 16;
            uint32_t bb[8][2];
#pragma unroll
            for (int ng = 0; ng < 8; ng++) {
                const __half* hr = hts + (ng * 8 + g) * HT_PITCH + jb;
                bb[ng][0] = *reinterpret_cast<const uint32_t*>(hr + t2);
                bb[ng][1] = *reinterpret_cast<const uint32_t*>(hr + t2 + 8);
            }
#pragma unroll
            for (int ig = 0; ig < 2; ig++) {
                const int* ap  = abuf + (ig * 16 + g) * ADJ_PITCH + js * 16;
                const int* ap8 = ap + 8 * ADJ_PITCH;
                int2 v00 = *reinterpret_cast<const int2*>(ap + t2);
                int2 v10 = *reinterpret_cast<const int2*>(ap8 + t2);
                int2 v01 = *reinterpret_cast<const int2*>(ap + t2 + 8);
                int2 v11 = *reinterpret_cast<const int2*>(ap8 + t2 + 8);
                uint32_t a0 = onehot2(v00.x, v00.y, kw);
                uint32_t a1 = onehot2(v10.x, v10.y, kw);
                uint32_t a2 = onehot2(v01.x, v01.y, kw);
                uint32_t a3 = onehot2(v11.x, v11.y, kw);
#pragma unroll
                for (int ng = 0; ng < 8; ng++)
                    mma16816(acc[ig][ng], a0, a1, a2, a3, bb[ng][0], bb[ng][1]);
            }
        }
    }
    __syncthreads();   // protect hts region before sred overlay

    // ---- phase 1: pack ALL acc -> fp16 A-fragments (acc dies here) ---------
    uint32_t ah[2][4][4];
#pragma unroll
    for (int ig = 0; ig < 2; ig++)
#pragma unroll
        for (int dc = 0; dc < 4; dc++) {
            const float* cA = acc[ig][2 * dc];
            const float* cB = acc[ig][2 * dc + 1];
            ah[ig][dc][0] = packh2(cA[0], cA[1]);
            ah[ig][dc][1] = packh2(cA[2], cA[3]);
            ah[ig][dc][2] = packh2(cB[0], cB[1]);
            ah[ig][dc][3] = packh2(cB[2], cB[3]);
        }

    // ---- phase 2: epilogue P[i][n] = sum_e S[i][e] * W[k][n][e] ------------
    float oacc[2][8][4];
#pragma unroll
    for (int ig = 0; ig < 2; ig++)
#pragma unroll
        for (int ng = 0; ng < 8; ng++)
#pragma unroll
            for (int q = 0; q < 4; q++) oacc[ig][ng][q] = 0.f;

    const __half* wg = g_Wh[dir] + (size_t)w * D_ * D_;   // [64 n][64 e]
#pragma unroll
    for (int dc = 0; dc < 4; dc++) {
#pragma unroll
        for (int ng = 0; ng < 8; ng++) {
            const __half* wr = wg + (ng * 8 + g) * D_ + dc * 16;
            uint32_t b0 = *reinterpret_cast<const uint32_t*>(wr + t2);
            uint32_t b1 = *reinterpret_cast<const uint32_t*>(wr + t2 + 8);
            mma16816(oacc[0][ng], ah[0][dc][0], ah[0][dc][1], ah[0][dc][2], ah[0][dc][3], b0, b1);
            mma16816(oacc[1][ng], ah[1][dc][0], ah[1][dc][1], ah[1][dc][2], ah[1][dc][3], b0, b1);
        }
    }

    // ---- cross-k reduction via smem (reuse hT region) ----------------------
    float* sr = sred + (size_t)w * 32 * SRED_PITCH;
#pragma unroll
    for (int ig = 0; ig < 2; ig++)
#pragma unroll
        for (int ng = 0; ng < 8; ng++) {
            float2 lo = make_float2(oacc[ig][ng][0], oacc[ig][ng][1]);
            float2 hi = make_float2(oacc[ig][ng][2], oacc[ig][ng][3]);
            *reinterpret_cast<float2*>(&sr[(ig * 16 + g) * SRED_PITCH + ng * 8 + t2])     = lo;
            *reinterpret_cast<float2*>(&sr[(ig * 16 + g + 8) * SRED_PITCH + ng * 8 + t2]) = hi;
        }
    __syncthreads();

    // ---- final sum over 8 warps + bias + store ------------------------------
    {
        int r  = tid >> 3;            // 0..31 (i row)
        int nb = (tid & 7) * 8;       // 0..56 (n col base)
        float s[8];
#pragma unroll
        for (int u = 0; u < 8; u++) s[u] = 0.f;
#pragma unroll
        for (int ww = 0; ww < 8; ww++) {
            const float* p = sred + (size_t)(ww * 32 + r) * SRED_PITCH + nb;
#pragma unroll
            for (int u = 0; u < 8; u++) s[u] += p[u];
        }
        const float* bp = bias + dir * 64 + nb;
        float* op = &out[(size_t)((b * N_) + i0 + r) * 128 + dir * 64 + nb];
        float4 o0, o1;
        o0.x = s[0] + bp[0]; o0.y = s[1] + bp[1]; o0.z = s[2] + bp[2]; o0.w = s[3] + bp[3];
        o1.x = s[4] + bp[4]; o1.y = s[5] + bp[5]; o1.z = s[6] + bp[6]; o1.w = s[7] + bp[7];
        *reinterpret_cast<float4*>(op)     = o0;
        *reinterpret_cast<float4*>(op + 4) = o1;
    }
}

// ---------------- launch ----------------------------------------------------
extern "C" void kernel_launch(void* const* d_in, const int* in_sizes, int n_in,
                              void* d_out, int out_size) {
    const float* h     = (const float*)d_in[0];   // [16,512,64]
    const int*   adj   = (const int*)d_in[1];     // [16,512,512]
    const float* min_  = (const float*)d_in[3];   // [8,64,64]
    const float* mout_ = (const float*)d_in[4];   // [8,64,64]
    const float* bias  = (const float*)d_in[5];   // [128]
    float* out = (float*)d_out;                   // [16,512,128]

    static int cfg = 0;
    if (!cfg) {
        cudaFuncSetAttribute(fused, cudaFuncAttributeMaxDynamicSharedMemorySize, SB_SMEM);
        cfg = 1;
    }

    prep<<<768, dim3(32, 8)>>>(h, min_, mout_);
    fused<<<512, 256, SB_SMEM>>>(adj, bias, out);  // 2 dir x 16 b x 16 itiles
}

// round 8
// speedup vs baseline: 5.8277x; 1.1303x over previous
#include <cuda_runtime.h>
#include <cuda_fp16.h>
#include <cstdint>

#define B_ 16
#define N_ 512
#define D_ 64
#define K_ 8

// ---------------- static device scratch -----------------------------------
__device__ __align__(16) __half   g_hT16[B_ * D_ * N_];        // [b][e][j] 1 MB
__device__ __align__(16) uint32_t g_Wf[2][K_][4][32][16];      // frag-packed W, 128 KB

// pitches
#define HT_PITCH   520   // halves per e-row (1040 B: LDSM rows tile all banks)
#define ADJ_PITCH  72    // int16 per i-row (144 B rows; 16B-aligned, conflict-free)
#define SRED_PITCH 66    // floats per i-row

// smem byte layout (sred overlays hT after the main loop)
#define OFF_HT   0
#define SZ_HT    (D_ * HT_PITCH * 2)             // 66560
#define OFF_ADJ  67584
#define SZ_ADJ   (32 * ADJ_PITCH * 2)            // 4608 per buffer (int16)
#define SB_SMEM  (OFF_ADJ + 2 * SZ_ADJ)          // 76800 -> 2 CTAs/SM

// ---------------- mma.sync m16n8k16 f16->f32 -------------------------------
__device__ __forceinline__ void mma16816(float* d,
                                         uint32_t a0, uint32_t a1, uint32_t a2, uint32_t a3,
                                         uint32_t b0, uint32_t b1) {
    asm volatile(
        "mma.sync.aligned.m16n8k16.row.col.f32.f16.f16.f32 "
        "{%0,%1,%2,%3}, {%4,%5,%6,%7}, {%8,%9}, {%0,%1,%2,%3};"
        : "+f"(d[0]), "+f"(d[1]), "+f"(d[2]), "+f"(d[3])
        : "r"(a0), "r"(a1), "r"(a2), "r"(a3), "r"(b0), "r"(b1));
}

__device__ __forceinline__ void ldsm_x4(uint32_t& r0, uint32_t& r1,
                                        uint32_t& r2, uint32_t& r3, uint32_t addr) {
    asm volatile("ldmatrix.sync.aligned.m8n8.x4.shared.b16 {%0,%1,%2,%3}, [%4];"
                 : "=r"(r0), "=r"(r1), "=r"(r2), "=r"(r3) : "r"(addr));
}

__device__ __forceinline__ uint32_t smem_u32(const void* p) {
    uint32_t a;
    asm("{ .reg .u64 t; cvta.to.shared.u64 t, %1; cvt.u32.u64 %0, t; }" : "=r"(a) : "l"(p));
    return a;
}

__device__ __forceinline__ uint32_t packh2(float x, float y) {
    __half2 h = __floats2half2_rn(x, y);
    return *reinterpret_cast<uint32_t*>(&h);
}

// ---------------- kernel 1: prep (hT fp16 transpose + W frag pack) ---------
__global__ void prep(const float* __restrict__ h,
                     const float* __restrict__ min_, const float* __restrict__ mout_) {
    int bid = blockIdx.x;
    int tx = threadIdx.x, ty = threadIdx.y;        // 32 x 8
    if (bid < 512) {
        __shared__ float tile[32][33];
        int j0 = (bid & 15) * 32;
        int e0 = ((bid >> 4) & 1) * 32;
        int b  = bid >> 5;
#pragma unroll
        for (int r = 0; r < 32; r += 8)
            tile[ty + r][tx] = h[((size_t)b * N_ + j0 + ty + r) * D_ + e0 + tx];
        __syncthreads();
#pragma unroll
        for (int r = 0; r < 32; r += 8)
            g_hT16[((size_t)b * D_ + e0 + ty + r) * N_ + j0 + tx] =
                __float2half_rn(tile[tx][ty + r]);
    } else {
        // W fragment pack: idx bits [q:1][ng:3][lane:5][dc:2][k:3][dir:1]
        int idx  = (bid - 512) * 256 + ty * 32 + tx;   // 0..32767
        int q    = idx & 1;
        int ng   = (idx >> 1) & 7;
        int lane = (idx >> 4) & 31;
        int dc   = (idx >> 9) & 3;
        int k    = (idx >> 11) & 7;
        int dir  = (idx >> 14) & 1;
        int e = dc * 16 + (lane & 3) * 2 + q * 8;
        int n = ng * 8 + (lane >> 2);
        const float* src = (dir ? mout_ : min_) + ((size_t)(k * 64 + n)) * 64 + e;
        g_Wf[dir][k][dc][lane][ng * 2 + q] =
            packh2(src[0], src[1]);
    }
}

// ---------------- kernel 2: fused one-hot HMMA + weight GEMM ---------------
// CTA = (dir, b, 32-row i tile). Warp w handles edge type k = w+1.
__global__ __launch_bounds__(256, 2)
void fused(const int* __restrict__ adj, const float* __restrict__ bias,
           float* __restrict__ out) {
    extern __shared__ char sm[];
    __half* hts  = reinterpret_cast<__half*>(sm + OFF_HT);
    float*  sred = reinterpret_cast<float*>(sm + OFF_HT);   // reuse after mainloop

    int tid = threadIdx.x, lane = tid & 31, w = tid >> 5;
    int job   = blockIdx.x;
    int itile = job & 15;
    int b     = (job >> 4) & 15;
    int dir   = job >> 8;
    int i0    = itile * 32;
    int kw    = w + 1;
    uint32_t kk2 = (uint32_t)kw | ((uint32_t)kw << 16);
    int t2    = (lane & 3) * 2;
    int g     = lane >> 2;

    const int* adjb = adj + (size_t)b * N_ * N_;

    // ---- cooperative load: hT (64KB fp16) into smem ------------------------
    {
        const uint4* src = reinterpret_cast<const uint4*>(g_hT16 + (size_t)b * D_ * N_);
#pragma unroll
        for (int s = 0; s < 16; s++) {
            int gg = tid + s * 256;               // 4096 uint4
            int e = gg >> 6, c = gg & 63;
            *reinterpret_cast<uint4*>(reinterpret_cast<char*>(hts)
                                      + e * (HT_PITCH * 2) + c * 16) = src[gg];
        }
    }

    // ldmatrix per-lane base address (e row + j half selection)
    uint32_t lm_base = smem_u32(hts)
                     + ((lane & 7) + ((lane >> 4) & 1) * 8) * (HT_PITCH * 2)
                     + ((lane >> 3) & 1) * 16;

    // ---- prefetch adj chunk 0 ----------------------------------------------
    int4 p0, p1;
    if (dir == 0) {
        int row = tid >> 3, cb = (tid & 7) * 8;
        const int* s = &adjb[(size_t)(i0 + row) * N_ + cb];
        p0 = *reinterpret_cast<const int4*>(s);
        p1 = *reinterpret_cast<const int4*>(s + 4);
    } else {
        int jr = tid >> 2, ib = (tid & 3) * 8;
        const int* s = &adjb[(size_t)jr * N_ + i0 + ib];
        p0 = *reinterpret_cast<const int4*>(s);
        p1 = *reinterpret_cast<const int4*>(s + 4);
    }

    float acc[2][8][4];
#pragma unroll
    for (int ig = 0; ig < 2; ig++)
#pragma unroll
        for (int ng = 0; ng < 8; ng++)
#pragma unroll
            for (int q = 0; q < 4; q++) acc[ig][ng][q] = 0.f;

    // ---- main loop: 8 chunks of 64 j, double-buffered int16 adj ------------
    for (int c = 0; c < 8; c++) {
        char* abase = sm + OFF_ADJ + (c & 1) * SZ_ADJ;
        if (dir == 0) {
            int row = tid >> 3, cb = (tid & 7) * 8;
            uint4 pk;
            pk.x = (uint32_t)(p0.x & 0xFFFF) | ((uint32_t)p0.y << 16);
            pk.y = (uint32_t)(p0.z & 0xFFFF) | ((uint32_t)p0.w << 16);
            pk.z = (uint32_t)(p1.x & 0xFFFF) | ((uint32_t)p1.y << 16);
            pk.w = (uint32_t)(p1.z & 0xFFFF) | ((uint32_t)p1.w << 16);
            *reinterpret_cast<uint4*>(abase + row * (ADJ_PITCH * 2) + cb * 2) = pk;
        } else {
            int jr = tid >> 2, ib = (tid & 3) * 8;
            unsigned short* a16 = reinterpret_cast<unsigned short*>(abase);
            a16[(ib + 0) * ADJ_PITCH + jr] = (unsigned short)p0.x;
            a16[(ib + 1) * ADJ_PITCH + jr] = (unsigned short)p0.y;
            a16[(ib + 2) * ADJ_PITCH + jr] = (unsigned short)p0.z;
            a16[(ib + 3) * ADJ_PITCH + jr] = (unsigned short)p0.w;
            a16[(ib + 4) * ADJ_PITCH + jr] = (unsigned short)p1.x;
            a16[(ib + 5) * ADJ_PITCH + jr] = (unsigned short)p1.y;
            a16[(ib + 6) * ADJ_PITCH + jr] = (unsigned short)p1.z;
            a16[(ib + 7) * ADJ_PITCH + jr] = (unsigned short)p1.w;
        }
        __syncthreads();

        if (c < 7) {
            int j0n = (c + 1) * 64;
            if (dir == 0) {
                int row = tid >> 3, cb = (tid & 7) * 8;
                const int* s = &adjb[(size_t)(i0 + row) * N_ + j0n + cb];
                p0 = *reinterpret_cast<const int4*>(s);
                p1 = *reinterpret_cast<const int4*>(s + 4);
            } else {
                int jr = tid >> 2, ib = (tid & 3) * 8;
                const int* s = &adjb[(size_t)(j0n + jr) * N_ + i0 + ib];
                p0 = *reinterpret_cast<const int4*>(s);
                p1 = *reinterpret_cast<const int4*>(s + 4);
            }
        }

        const uint32_t* a32 = reinterpret_cast<const uint32_t*>(abase);
#pragma unroll
        for (int js = 0; js < 4; js++) {
            // B fragments: 4x ldmatrix.x4 (16 regs)
            uint32_t bb[8][2];
#pragma unroll
            for (int p = 0; p < 4; p++) {
                uint32_t addr = lm_base + p * (16 * HT_PITCH * 2) + c * 128 + js * 32;
                ldsm_x4(bb[2 * p][0], bb[2 * p][1], bb[2 * p + 1][0], bb[2 * p + 1][1], addr);
            }
#pragma unroll
            for (int ig = 0; ig < 2; ig++) {
                int rw = (ig * 16 + g) * (ADJ_PITCH / 2) + js * 8 + (lane & 3);
                uint32_t v00 = a32[rw];
                uint32_t v01 = a32[rw + 4];
                uint32_t v10 = a32[rw + 8 * (ADJ_PITCH / 2)];
                uint32_t v11 = a32[rw + 8 * (ADJ_PITCH / 2) + 4];
                uint32_t a0 = __vcmpeq2(v00, kk2) & 0x3C003C00u;
                uint32_t a1 = __vcmpeq2(v10, kk2) & 0x3C003C00u;
                uint32_t a2 = __vcmpeq2(v01, kk2) & 0x3C003C00u;
                uint32_t a3 = __vcmpeq2(v11, kk2) & 0x3C003C00u;
#pragma unroll
                for (int ng = 0; ng < 8; ng++)
                    mma16816(acc[ig][ng], a0, a1, a2, a3, bb[ng][0], bb[ng][1]);
            }
        }
    }
    __syncthreads();   // protect hts region before sred overlay

    // ---- phase 1: pack ALL acc -> fp16 A-fragments (acc dies here) ---------
    uint32_t ah[2][4][4];
#pragma unroll
    for (int ig = 0; ig < 2; ig++)
#pragma unroll
        for (int dc = 0; dc < 4; dc++) {
            const float* cA = acc[ig][2 * dc];
            const float* cB = acc[ig][2 * dc + 1];
            ah[ig][dc][0] = packh2(cA[0], cA[1]);
            ah[ig][dc][1] = packh2(cA[2], cA[3]);
            ah[ig][dc][2] = packh2(cB[0], cB[1]);
            ah[ig][dc][3] = packh2(cB[2], cB[3]);
        }

    // ---- phase 2: epilogue P[i][n] = sum_e S[i][e] * W[k][n][e] ------------
    float oacc[2][8][4];
#pragma unroll
    for (int ig = 0; ig < 2; ig++)
#pragma unroll
        for (int ng = 0; ng < 8; ng++)
#pragma unroll
            for (int q = 0; q < 4; q++) oacc[ig][ng][q] = 0.f;

    const uint4* wfp = reinterpret_cast<const uint4*>(&g_Wf[dir][w][0][lane][0]);
#pragma unroll
    for (int dc = 0; dc < 4; dc++) {
        uint4 w0 = wfp[dc * 128 + 0];
        uint4 w1 = wfp[dc * 128 + 1];
        uint4 w2 = wfp[dc * 128 + 2];
        uint4 w3 = wfp[dc * 128 + 3];
        uint32_t wb[8][2] = {
            {w0.x, w0.y}, {w0.z, w0.w}, {w1.x, w1.y}, {w1.z, w1.w},
            {w2.x, w2.y}, {w2.z, w2.w}, {w3.x, w3.y}, {w3.z, w3.w}};
#pragma unroll
        for (int ng = 0; ng < 8; ng++) {
            mma16816(oacc[0][ng], ah[0][dc][0], ah[0][dc][1], ah[0][dc][2], ah[0][dc][3],
                     wb[ng][0], wb[ng][1]);
            mma16816(oacc[1][ng], ah[1][dc][0], ah[1][dc][1], ah[1][dc][2], ah[1][dc][3],
                     wb[ng][0], wb[ng][1]);
        }
    }

    // ---- cross-k reduction via smem (reuse hT region) ----------------------
    float* sr = sred + (size_t)w * 32 * SRED_PITCH;
#pragma unroll
    for (int ig = 0; ig < 2; ig++)
#pragma unroll
        for (int ng = 0; ng < 8; ng++) {
            float2 lo = make_float2(oacc[ig][ng][0], oacc[ig][ng][1]);
            float2 hi = make_float2(oacc[ig][ng][2], oacc[ig][ng][3]);
            *reinterpret_cast<float2*>(&sr[(ig * 16 + g) * SRED_PITCH + ng * 8 + t2])     = lo;
            *reinterpret_cast<float2*>(&sr[(ig * 16 + g + 8) * SRED_PITCH + ng * 8 + t2]) = hi;
        }
    __syncthreads();

    // ---- final sum over 8 warps + bias + store ------------------------------
    {
        int r  = tid >> 3;            // 0..31 (i row)
        int nb = (tid & 7) * 8;       // 0..56 (n col base)
        float s[8];
#pragma unroll
        for (int u = 0; u < 8; u++) s[u] = 0.f;
#pragma unroll
        for (int ww = 0; ww < 8; ww++) {
            const float* p = sred + (size_t)(ww * 32 + r) * SRED_PITCH + nb;
#pragma unroll
            for (int u = 0; u < 8; u++) s[u] += p[u];
        }
        const float* bp = bias + dir * 64 + nb;
        float* op = &out[(size_t)((b * N_) + i0 + r) * 128 + dir * 64 + nb];
        float4 o0, o1;
        o0.x = s[0] + bp[0]; o0.y = s[1] + bp[1]; o0.z = s[2] + bp[2]; o0.w = s[3] + bp[3];
        o1.x = s[4] + bp[4]; o1.y = s[5] + bp[5]; o1.z = s[6] + bp[6]; o1.w = s[7] + bp[7];
        *reinterpret_cast<float4*>(op)     = o0;
        *reinterpret_cast<float4*>(op + 4) = o1;
    }
}

// ---------------- launch ----------------------------------------------------
extern "C" void kernel_launch(void* const* d_in, const int* in_sizes, int n_in,
                              void* d_out, int out_size) {
    const float* h     = (const float*)d_in[0];   // [16,512,64]
    const int*   adj   = (const int*)d_in[1];     // [16,512,512]
    const float* min_  = (const float*)d_in[3];   // [8,64,64]
    const float* mout_ = (const float*)d_in[4];   // [8,64,64]
    const float* bias  = (const float*)d_in[5];   // [128]
    float* out = (float*)d_out;                   // [16,512,128]

    static int cfg = 0;
    if (!cfg) {
        cudaFuncSetAttribute(fused, cudaFuncAttributeMaxDynamicSharedMemorySize, SB_SMEM);
        cfg = 1;
    }

    prep<<<640, dim3(32, 8)>>>(h, min_, mout_);
    fused<<<512, 256, SB_SMEM>>>(adj, bias, out);  // 2 dir x 16 b x 16 itiles
}